// round 11
// baseline (speedup 1.0000x reference)
#include <cuda_runtime.h>
#include <math_constants.h>

#define FULL_MASK 0xFFFFFFFFu
#define CLAMP_V 1000000.0f

struct cfv { float r, i; };

// jnp.nan_to_num(nan=0, posinf=1e6, neginf=-1e6) then clip(-1e6, 1e6)
__device__ __forceinline__ float sanit(float v) {
    if (!(v == v)) return 0.0f;                 // NaN -> +0
    return fminf(CLAMP_V, fmaxf(-CLAMP_V, v));  // +-inf clamp too
}

// log|r + i*j|, XLA-style scaled abs (max*sqrt(1+(min/max)^2)), RN, no FMA.
__device__ __forceinline__ float xla_log_abs(float r, float i) {
    float ar = fabsf(r), ai = fabsf(i);
    float mx = fmaxf(ar, ai), mn = fminf(ar, ai);
    float d  = __fdiv_rn(mn, mx);
    float a  = __fmul_rn(mx, sqrtf(__fadd_rn(1.0f, __fmul_rn(d, d))));
    if (mx == 0.0f || isinf(mn)) a = mx;        // 0 -> -inf; inf -> inf
    return logf(a);
}

// exp( (lur+i*lui)*(lvr+i*lvi) ): naive complex mul, exp/cos/sin, sanitize.
__device__ __forceinline__ cfv eml_core(float lur, float lui, float lvr, float lvi) {
    float wr = __fsub_rn(__fmul_rn(lur, lvr), __fmul_rn(lui, lvi));
    float wi = __fadd_rn(__fmul_rn(lur, lvi), __fmul_rn(lui, lvr));
    float e = expf(wr);
    float c = cosf(wi);
    float s = sinf(wi);
    cfv o;
    o.r = sanit(__fmul_rn(e, c));
    o.i = sanit(__fmul_rn(e, s));
    return o;
}

__device__ __forceinline__ cfv eml_cc(cfv u, cfv v) {
    float lur = xla_log_abs(u.r, u.i);
    float lui = atan2f(u.i, u.r);
    float lvr = xla_log_abs(v.r, v.i);
    float lvi = atan2f(v.i, v.r);
    return eml_core(lur, lui, lvr, lvi);
}

// Level-0 inputs are (real, +0): abs == |u| exactly, arg == 0 / +pi by signbit.
__device__ __forceinline__ cfv eml_rr(float u, float v) {
    float lur = logf(fabsf(u));
    float lui = signbit(u) ? CUDART_PI_F : 0.0f;
    float lvr = logf(fabsf(v));
    float lvi = signbit(v) ? CUDART_PI_F : 0.0f;
    return eml_core(lur, lui, lvr, lvi);
}

// (g0 + g1*x_b) + g2*child in complex arithmetic, x_b = (x, +0).
// Imag chain starts at +0, so any -0 product canonicalizes to +0.
__device__ __forceinline__ cfv gate_apply(float g0, float g1, float g2,
                                          float xv, cfv ch) {
    cfv o;
    o.r = __fadd_rn(__fadd_rn(g0, __fmul_rn(g1, xv)), __fmul_rn(g2, ch.r));
    o.i = __fadd_rn(0.0f, __fmul_rn(g2, ch.i));
    return o;
}

// One warp per batch element. Lane owns leaves [lane*32, lane*32+32):
// levels 0-4 fully in registers, levels 5-9 via shfl compaction.
// writeImag selects output layout: interleaved complex vs real-part only.
__global__ __launch_bounds__(128)
void eml_tree_kernel(const float* __restrict__ x,
                     const float* __restrict__ leaf,   // (1024, 2)
                     const float* __restrict__ gate,   // (1023, 2, 3)
                     float* __restrict__ out,
                     int batch, int writeImag) {
    const int gtid = blockIdx.x * blockDim.x + threadIdx.x;
    const int warp = gtid >> 5;
    const int lane = threadIdx.x & 31;
    if (warp >= batch) return;

    const float xv = __ldg(&x[warp]);
    const float2* __restrict__ leaf2 = (const float2*)leaf;
    const float2* __restrict__ gate2 = (const float2*)gate;

    cfv v[16];
    const int base = lane * 32;

    // ---- level 0: 16 pairs per lane, purely real arithmetic ----
    #pragma unroll
    for (int j = 0; j < 16; j++) {
        float2 la = __ldg(leaf2 + base + 2 * j);
        float2 lb = __ldg(leaf2 + base + 2 * j + 1);
        float L = __fadd_rn(la.x, __fmul_rn(la.y, xv));
        float R = __fadd_rn(lb.x, __fmul_rn(lb.y, xv));
        int gi = lane * 16 + j;
        float2 gA = __ldg(gate2 + gi * 3);      // (g00, g01)
        float2 gB = __ldg(gate2 + gi * 3 + 1);  // (g02, g10)
        float2 gC = __ldg(gate2 + gi * 3 + 2);  // (g11, g12)
        float u = __fadd_rn(__fadd_rn(gA.x, __fmul_rn(gA.y, xv)), __fmul_rn(gB.x, L));
        float w = __fadd_rn(__fadd_rn(gB.y, __fmul_rn(gC.x, xv)), __fmul_rn(gC.y, R));
        v[j] = eml_rr(u, w);
    }

    // ---- levels 1-4: in-register compaction ----
    int off = 512;
    #pragma unroll
    for (int m = 16; m >= 2; m >>= 1) {
        const int np = m >> 1;
        #pragma unroll
        for (int j = 0; j < np; j++) {
            int gi = off + lane * np + j;
            float2 gA = __ldg(gate2 + gi * 3);
            float2 gB = __ldg(gate2 + gi * 3 + 1);
            float2 gC = __ldg(gate2 + gi * 3 + 2);
            cfv u = gate_apply(gA.x, gA.y, gB.x, xv, v[2 * j]);
            cfv w = gate_apply(gB.y, gC.x, gC.y, xv, v[2 * j + 1]);
            v[j] = eml_cc(u, w);
        }
        off += 32 * np;
    }
    // off == 992

    // ---- levels 5-9: warp shuffle compaction ----
    cfv val = v[0];
    #pragma unroll
    for (int m = 32; m >= 2; m >>= 1) {
        const int np = m >> 1;
        float lr = __shfl_sync(FULL_MASK, val.r, 2 * lane);
        float li = __shfl_sync(FULL_MASK, val.i, 2 * lane);
        float rr = __shfl_sync(FULL_MASK, val.r, 2 * lane + 1);
        float ri = __shfl_sync(FULL_MASK, val.i, 2 * lane + 1);
        int k = (lane < np) ? lane : 0;   // clamp gate index for inactive lanes
        int gi = off + k;
        float2 gA = __ldg(gate2 + gi * 3);
        float2 gB = __ldg(gate2 + gi * 3 + 1);
        float2 gC = __ldg(gate2 + gi * 3 + 2);
        cfv l; l.r = lr; l.i = li;
        cfv r; r.r = rr; r.i = ri;
        cfv u = gate_apply(gA.x, gA.y, gB.x, xv, l);
        cfv w = gate_apply(gB.y, gC.x, gC.y, xv, r);
        val = eml_cc(u, w);
        off += np;
    }
    // off == 1023; lane 0 holds the root

    if (lane == 0) {
        if (writeImag) {
            ((float2*)out)[warp] = make_float2(val.r, val.i);
        } else {
            out[warp] = val.r;    // __output__ is float32 real part
        }
    }
}

extern "C" void kernel_launch(void* const* d_in, const int* in_sizes, int n_in,
                              void* d_out, int out_size) {
    // Size-based binding, correct under any ordering of the three inputs.
    const float* x    = nullptr;
    const float* leaf = nullptr;
    const float* gate = nullptr;
    int batch = 0;
    for (int k = 0; k < n_in; k++) {
        if (in_sizes[k] == 2048)       leaf = (const float*)d_in[k];
        else if (in_sizes[k] == 6138)  gate = (const float*)d_in[k];
        else                           { x = (const float*)d_in[k]; batch = in_sizes[k]; }
    }

    // R10 diagnosis: rel_err == 0.7074 across bit-different-but-equivalent
    // kernels == interleaved-complex writes compared against a REAL-ONLY
    // float32 reference (im ~= 0, re ~= 1 for the calm majority -> rel^2 ~= 0.5).
    // Use out_size to pick the layout: out_size == batch -> real part only;
    // out_size >= 2*batch -> interleaved complex64.
    const int writeImag = (out_size >= 2 * batch) ? 1 : 0;

    const int threads = 128;                    // 4 warps / block
    const int warps_per_block = threads / 32;
    const int blocks = (batch + warps_per_block - 1) / warps_per_block;

    eml_tree_kernel<<<blocks, threads>>>(x, leaf, gate, (float*)d_out,
                                         batch, writeImag);
}

// round 12
// speedup vs baseline: 1.7260x; 1.7260x over previous
#include <cuda_runtime.h>
#include <math_constants.h>

#define FULL_MASK 0xFFFFFFFFu
#define CLAMP_V 1000000.0f

struct cfv { float r, i; };

// jnp.nan_to_num(nan=0, posinf=1e6, neginf=-1e6) then clip(-1e6, 1e6)
__device__ __forceinline__ float sanit(float v) {
    if (!(v == v)) return 0.0f;                 // NaN -> +0
    return fminf(CLAMP_V, fmaxf(-CLAMP_V, v));  // +-inf clamp too
}

// log|r + i*j|. Fast path: 0.5*__logf(r^2+i^2) (safe: mx>1e-15 -> mx^2 normal).
// Rare scaled path prevents the -inf/NaN divergence for tiny-but-nonzero |z|.
__device__ __forceinline__ float fast_log_abs(float r, float i) {
    float ar = fabsf(r), ai = fabsf(i);
    float mx = fmaxf(ar, ai);
    if (mx > 1e-15f)
        return 0.5f * __logf(fmaf(ar, ar, ai * ai));
    if (mx == 0.0f) return -CUDART_INF_F;
    float mn = fminf(ar, ai);
    float d = __fdividef(mn, mx);
    return __logf(mx) + 0.5f * log1pf(d * d);
}

// Minimax atan2, max err ~6e-7 rad. r >= 0 before the final sign transfer,
// so OR-ing in sign(y) == copysign(r, y). Exact at y=+0: t=0 -> r=0 or pi.
__device__ __forceinline__ float fast_atan2(float y, float x) {
    float ax = fabsf(x), ay = fabsf(y);
    float mx = fmaxf(ax, ay), mn = fminf(ax, ay);
    float t = (mx == 0.0f) ? 0.0f : __fdividef(mn, mx);
    float t2 = t * t;
    float p =          -0.01172120f;
    p = fmaf(p, t2,  0.05265332f);
    p = fmaf(p, t2, -0.11643287f);
    p = fmaf(p, t2,  0.19354346f);
    p = fmaf(p, t2, -0.33262347f);
    p = fmaf(p, t2,  0.99997726f);
    float r = p * t;
    if (ay > ax)    r = 1.5707963268f - r;
    if (signbit(x)) r = 3.1415926536f - r;
    return __uint_as_float(__float_as_uint(r) | (__float_as_uint(y) & 0x80000000u));
}

// exp( (lur+i*lui)*(lvr+i*lvi) ) then sanitize.
__device__ __forceinline__ cfv eml_core(float lur, float lui, float lvr, float lvi) {
    float wr = fmaf(lur, lvr, -(lui * lvi));
    float wi = fmaf(lur, lvi,   lui * lvr);
    float e = __expf(wr);
    float s, c;
    sincosf(wi, &s, &c);
    cfv o;
    o.r = sanit(e * c);
    o.i = sanit(e * s);
    return o;
}

__device__ __forceinline__ cfv eml_cc(cfv u, cfv v) {
    float lur = fast_log_abs(u.r, u.i);
    float lui = fast_atan2(u.i, u.r);
    float lvr = fast_log_abs(v.r, v.i);
    float lvi = fast_atan2(v.i, v.r);
    return eml_core(lur, lui, lvr, lvi);
}

// Level-0 inputs are (real, +0): abs == |u|, arg == 0 / +pi by signbit.
__device__ __forceinline__ cfv eml_rr(float u, float v) {
    float lur = __logf(fabsf(u));
    float lui = signbit(u) ? CUDART_PI_F : 0.0f;
    float lvr = __logf(fabsf(v));
    float lvi = signbit(v) ? CUDART_PI_F : 0.0f;
    return eml_core(lur, lui, lvr, lvi);
}

// (g0 + g1*x_b) + g2*child complex, x_b = (x, +0). The imag chain MUST
// canonicalize -0 products to +0 (reference semantics; R3 bug class) —
// keep the explicit +0 add, do not let it fold.
__device__ __forceinline__ cfv gate_apply(float g0, float g1, float g2,
                                          float xv, cfv ch) {
    cfv o;
    o.r = fmaf(g2, ch.r, fmaf(g1, xv, g0));
    o.i = __fadd_rn(0.0f, g2 * ch.i);
    return o;
}

// One warp per TWO batch elements: every param load amortizes over both
// (halves L1 traffic per element, doubles ILP). Levels 0-4 in registers,
// levels 5-9 via shfl compaction.
__global__ __launch_bounds__(128)
void eml_tree_kernel2(const float* __restrict__ x,
                      const float* __restrict__ leaf,   // (1024, 2)
                      const float* __restrict__ gate,   // (1023, 2, 3)
                      float* __restrict__ out,
                      int batch, int writeImag) {
    const int gtid = blockIdx.x * blockDim.x + threadIdx.x;
    const int warp = gtid >> 5;
    const int lane = threadIdx.x & 31;
    const int e0 = 2 * warp;
    const int e1 = e0 + 1;
    if (e0 >= batch) return;

    const float x0 = __ldg(&x[e0]);
    const float x1 = (e1 < batch) ? __ldg(&x[e1]) : 0.0f;

    const float2* __restrict__ leaf2 = (const float2*)leaf;
    const float2* __restrict__ gate2 = (const float2*)gate;

    cfv v0[16], v1[16];
    const int base = lane * 32;

    // ---- level 0: 16 pairs per lane, purely real arithmetic ----
    #pragma unroll
    for (int j = 0; j < 16; j++) {
        float2 la = __ldg(leaf2 + base + 2 * j);
        float2 lb = __ldg(leaf2 + base + 2 * j + 1);
        int gi = lane * 16 + j;
        float2 gA = __ldg(gate2 + gi * 3);      // (g00, g01)
        float2 gB = __ldg(gate2 + gi * 3 + 1);  // (g02, g10)
        float2 gC = __ldg(gate2 + gi * 3 + 2);  // (g11, g12)

        float L0 = fmaf(la.y, x0, la.x);
        float R0 = fmaf(lb.y, x0, lb.x);
        float u0 = fmaf(gB.x, L0, fmaf(gA.y, x0, gA.x));
        float w0 = fmaf(gC.y, R0, fmaf(gC.x, x0, gB.y));
        v0[j] = eml_rr(u0, w0);

        float L1 = fmaf(la.y, x1, la.x);
        float R1 = fmaf(lb.y, x1, lb.x);
        float u1 = fmaf(gB.x, L1, fmaf(gA.y, x1, gA.x));
        float w1 = fmaf(gC.y, R1, fmaf(gC.x, x1, gB.y));
        v1[j] = eml_rr(u1, w1);
    }

    // ---- levels 1-4: in-register compaction ----
    int off = 512;
    #pragma unroll
    for (int m = 16; m >= 2; m >>= 1) {
        const int np = m >> 1;
        #pragma unroll
        for (int j = 0; j < np; j++) {
            int gi = off + lane * np + j;
            float2 gA = __ldg(gate2 + gi * 3);
            float2 gB = __ldg(gate2 + gi * 3 + 1);
            float2 gC = __ldg(gate2 + gi * 3 + 2);

            cfv ua = gate_apply(gA.x, gA.y, gB.x, x0, v0[2 * j]);
            cfv wa = gate_apply(gB.y, gC.x, gC.y, x0, v0[2 * j + 1]);
            v0[j] = eml_cc(ua, wa);

            cfv ub = gate_apply(gA.x, gA.y, gB.x, x1, v1[2 * j]);
            cfv wb = gate_apply(gB.y, gC.x, gC.y, x1, v1[2 * j + 1]);
            v1[j] = eml_cc(ub, wb);
        }
        off += 32 * np;
    }
    // off == 992

    // ---- levels 5-9: warp shuffle compaction ----
    cfv a = v0[0];
    cfv b = v1[0];
    #pragma unroll
    for (int m = 32; m >= 2; m >>= 1) {
        const int np = m >> 1;
        float alr = __shfl_sync(FULL_MASK, a.r, 2 * lane);
        float ali = __shfl_sync(FULL_MASK, a.i, 2 * lane);
        float arr = __shfl_sync(FULL_MASK, a.r, 2 * lane + 1);
        float ari = __shfl_sync(FULL_MASK, a.i, 2 * lane + 1);
        float blr = __shfl_sync(FULL_MASK, b.r, 2 * lane);
        float bli = __shfl_sync(FULL_MASK, b.i, 2 * lane);
        float brr = __shfl_sync(FULL_MASK, b.r, 2 * lane + 1);
        float bri = __shfl_sync(FULL_MASK, b.i, 2 * lane + 1);

        int k = (lane < np) ? lane : 0;   // clamp gate index for inactive lanes
        int gi = off + k;
        float2 gA = __ldg(gate2 + gi * 3);
        float2 gB = __ldg(gate2 + gi * 3 + 1);
        float2 gC = __ldg(gate2 + gi * 3 + 2);

        cfv l0; l0.r = alr; l0.i = ali;
        cfv r0; r0.r = arr; r0.i = ari;
        cfv ua = gate_apply(gA.x, gA.y, gB.x, x0, l0);
        cfv wa = gate_apply(gB.y, gC.x, gC.y, x0, r0);
        a = eml_cc(ua, wa);

        cfv l1; l1.r = blr; l1.i = bli;
        cfv r1; r1.r = brr; r1.i = bri;
        cfv ub = gate_apply(gA.x, gA.y, gB.x, x1, l1);
        cfv wb = gate_apply(gB.y, gC.x, gC.y, x1, r1);
        b = eml_cc(ub, wb);

        off += np;
    }
    // off == 1023; lane 0 holds both roots

    if (lane == 0) {
        if (writeImag) {
            float2* o2 = (float2*)out;
            o2[e0] = make_float2(a.r, a.i);
            if (e1 < batch) o2[e1] = make_float2(b.r, b.i);
        } else {
            out[e0] = a.r;
            if (e1 < batch) out[e1] = b.r;
        }
    }
}

extern "C" void kernel_launch(void* const* d_in, const int* in_sizes, int n_in,
                              void* d_out, int out_size) {
    // Size-based binding, correct under any ordering of the three inputs.
    const float* x    = nullptr;
    const float* leaf = nullptr;
    const float* gate = nullptr;
    int batch = 0;
    for (int k = 0; k < n_in; k++) {
        if (in_sizes[k] == 2048)       leaf = (const float*)d_in[k];
        else if (in_sizes[k] == 6138)  gate = (const float*)d_in[k];
        else                           { x = (const float*)d_in[k]; batch = in_sizes[k]; }
    }

    // out_size == batch -> real-part-only float32; >= 2*batch -> interleaved c64.
    const int writeImag = (out_size >= 2 * batch) ? 1 : 0;

    const int nwarps = (batch + 1) / 2;           // 2 elements per warp
    const int threads = 128;                      // 4 warps per block
    const int blocks = (nwarps + 3) / 4;

    eml_tree_kernel2<<<blocks, threads>>>(x, leaf, gate, (float*)d_out,
                                          batch, writeImag);
}

// round 17
// speedup vs baseline: 2.7866x; 1.6145x over previous
#include <cuda_runtime.h>
#include <math_constants.h>

#define FULL_MASK 0xFFFFFFFFu
#define CLAMP_V 1000000.0f
#define NE 4   // batch elements per warp

struct cfv { float r, i; };

// jnp.nan_to_num(nan=0, posinf=1e6, neginf=-1e6) then clip(-1e6, 1e6)
__device__ __forceinline__ float sanit(float v) {
    if (!(v == v)) return 0.0f;
    return fminf(CLAMP_V, fmaxf(-CLAMP_V, v));
}

// log|r + i*j|. Fast path 0.5*__logf(r^2+i^2); guarded scaled path for tiny |z|.
__device__ __forceinline__ float fast_log_abs(float r, float i) {
    float ar = fabsf(r), ai = fabsf(i);
    float mx = fmaxf(ar, ai);
    if (mx > 1e-15f)
        return 0.5f * __logf(fmaf(ar, ar, ai * ai));
    if (mx == 0.0f) return -CUDART_INF_F;
    float mn = fminf(ar, ai);
    float d = __fdividef(mn, mx);
    return __logf(mx) + 0.5f * log1pf(d * d);
}

// Minimax atan2, max err ~6e-7 rad. Exact at y=+0 (t==0 -> 0 or pi).
__device__ __forceinline__ float fast_atan2(float y, float x) {
    float ax = fabsf(x), ay = fabsf(y);
    float mx = fmaxf(ax, ay), mn = fminf(ax, ay);
    float t = (mx == 0.0f) ? 0.0f : __fdividef(mn, mx);
    float t2 = t * t;
    float p =          -0.01172120f;
    p = fmaf(p, t2,  0.05265332f);
    p = fmaf(p, t2, -0.11643287f);
    p = fmaf(p, t2,  0.19354346f);
    p = fmaf(p, t2, -0.33262347f);
    p = fmaf(p, t2,  0.99997726f);
    float r = p * t;
    if (ay > ax)    r = 1.5707963268f - r;
    if (signbit(x)) r = 3.1415926536f - r;
    return __uint_as_float(__float_as_uint(r) | (__float_as_uint(y) & 0x80000000u));
}

// exp( (lur+i*lui)*(lvr+i*lvi) ) then sanitize. MUFU sin/cos (|wi| <~ 2e2).
__device__ __forceinline__ cfv eml_core(float lur, float lui, float lvr, float lvi) {
    float wr = fmaf(lur, lvr, -(lui * lvi));
    float wi = fmaf(lur, lvi,   lui * lvr);
    float e = __expf(wr);
    float s, c;
    __sincosf(wi, &s, &c);
    cfv o;
    o.r = sanit(e * c);
    o.i = sanit(e * s);
    return o;
}

__device__ __forceinline__ cfv eml_cc(cfv u, cfv v) {
    float lur = fast_log_abs(u.r, u.i);
    float lui = fast_atan2(u.i, u.r);
    float lvr = fast_log_abs(v.r, v.i);
    float lvi = fast_atan2(v.i, v.r);
    return eml_core(lur, lui, lvr, lvi);
}

// Level-0 inputs are (real, +0): abs == |u|, arg == 0 / +pi by signbit.
__device__ __forceinline__ cfv eml_rr(float u, float v) {
    float lur = __logf(fabsf(u));
    float lui = signbit(u) ? CUDART_PI_F : 0.0f;
    float lvr = __logf(fabsf(v));
    float lvi = signbit(v) ? CUDART_PI_F : 0.0f;
    return eml_core(lur, lui, lvr, lvi);
}

// (g0 + g1*x_b) + g2*child complex, x_b = (x, +0). Imag chain MUST
// canonicalize -0 products to +0 (reference semantics; R3 bug class).
__device__ __forceinline__ cfv gate_apply(float g0, float g1, float g2,
                                          float xv, cfv ch) {
    cfv o;
    o.r = fmaf(g2, ch.r, fmaf(g1, xv, g0));
    o.i = __fadd_rn(0.0f, g2 * ch.i);
    return o;
}

// One warp per NE=4 batch elements. Lane owns leaves [lane*32, lane*32+32),
// traversed post-order (binary counter) so only 5 pending roots are live:
// merge depths d=1..4 use gate offsets 512/768/896/960; cross-lane shfl
// phase covers offsets 992/1008/1016/1020/1022. Identical math + order to
// the level-order formulation (proven bit-equal in R10).
__global__ __launch_bounds__(128)
void eml_tree_kernel4(const float* __restrict__ x,
                      const float* __restrict__ leaf,   // (1024, 2)
                      const float* __restrict__ gate,   // (1023, 2, 3)
                      float* __restrict__ out,
                      int batch, int writeImag) {
    const int gtid = blockIdx.x * blockDim.x + threadIdx.x;
    const int warp = gtid >> 5;
    const int lane = threadIdx.x & 31;
    const int ebase = warp * NE;
    if (ebase >= batch) return;

    float xv[NE];
    #pragma unroll
    for (int e = 0; e < NE; e++)
        xv[e] = (ebase + e < batch) ? __ldg(&x[ebase + e]) : 0.0f;

    const float2* __restrict__ leaf2 = (const float2*)leaf;
    const float2* __restrict__ gate2 = (const float2*)gate;

    cfv st[NE][5];   // pending subtree roots, depth 1..5 (index d-1)
    cfv val[NE];
    const int base = lane * 32;

    #pragma unroll
    for (int ip = 0; ip < 16; ip++) {
        // ---- leaf pair + level-0 gate (purely real arithmetic) ----
        float2 la = __ldg(leaf2 + base + 2 * ip);
        float2 lb = __ldg(leaf2 + base + 2 * ip + 1);
        int gi0 = lane * 16 + ip;
        float2 gA = __ldg(gate2 + gi0 * 3);
        float2 gB = __ldg(gate2 + gi0 * 3 + 1);
        float2 gC = __ldg(gate2 + gi0 * 3 + 2);

        #pragma unroll
        for (int e = 0; e < NE; e++) {
            float L = fmaf(la.y, xv[e], la.x);
            float R = fmaf(lb.y, xv[e], lb.x);
            float u = fmaf(gB.x, L, fmaf(gA.y, xv[e], gA.x));
            float w = fmaf(gC.y, R, fmaf(gC.x, xv[e], gB.y));
            val[e] = eml_rr(u, w);
        }

        // ---- in-lane merges (depths 1..4), binary-counter post-order ----
        #pragma unroll
        for (int d = 1; d <= 4; d++) {
            if ((ip & ((1 << d) - 1)) != ((1 << d) - 1)) break;
            int gi = (1024 - (1024 >> d)) + lane * (16 >> d) + (ip >> d);
            float2 hA = __ldg(gate2 + gi * 3);
            float2 hB = __ldg(gate2 + gi * 3 + 1);
            float2 hC = __ldg(gate2 + gi * 3 + 2);
            #pragma unroll
            for (int e = 0; e < NE; e++) {
                cfv u = gate_apply(hA.x, hA.y, hB.x, xv[e], st[e][d - 1]);
                cfv w = gate_apply(hB.y, hC.x, hC.y, xv[e], val[e]);
                val[e] = eml_cc(u, w);
            }
        }

        // ---- push at resting depth (trailing ones of ip) ----
        int nm = __ffs(~ip) - 1;              // constant after unroll
        #pragma unroll
        for (int e = 0; e < NE; e++) st[e][nm] = val[e];
    }

    // lane's 32-leaf subtree root:
    #pragma unroll
    for (int e = 0; e < NE; e++) val[e] = st[e][4];

    // ---- cross-lane levels: offsets 992, 1008, 1016, 1020, 1022 ----
    int off = 992;
    #pragma unroll
    for (int m = 32; m >= 2; m >>= 1) {
        const int np = m >> 1;
        float lr[NE], li[NE], rr[NE], ri[NE];
        #pragma unroll
        for (int e = 0; e < NE; e++) {
            lr[e] = __shfl_sync(FULL_MASK, val[e].r, 2 * lane);
            li[e] = __shfl_sync(FULL_MASK, val[e].i, 2 * lane);
            rr[e] = __shfl_sync(FULL_MASK, val[e].r, 2 * lane + 1);
            ri[e] = __shfl_sync(FULL_MASK, val[e].i, 2 * lane + 1);
        }
        int k = (lane < np) ? lane : 0;       // clamp for inactive lanes
        int gi = off + k;
        float2 gA = __ldg(gate2 + gi * 3);
        float2 gB = __ldg(gate2 + gi * 3 + 1);
        float2 gC = __ldg(gate2 + gi * 3 + 2);
        #pragma unroll
        for (int e = 0; e < NE; e++) {
            cfv l; l.r = lr[e]; l.i = li[e];
            cfv r; r.r = rr[e]; r.i = ri[e];
            cfv u = gate_apply(gA.x, gA.y, gB.x, xv[e], l);
            cfv w = gate_apply(gB.y, gC.x, gC.y, xv[e], r);
            val[e] = eml_cc(u, w);
        }
        off += np;
    }
    // off == 1023; lane 0 holds the roots

    if (lane == 0) {
        #pragma unroll
        for (int e = 0; e < NE; e++) {
            if (ebase + e < batch) {
                if (writeImag)
                    ((float2*)out)[ebase + e] = make_float2(val[e].r, val[e].i);
                else
                    out[ebase + e] = val[e].r;
            }
        }
    }
}

extern "C" void kernel_launch(void* const* d_in, const int* in_sizes, int n_in,
                              void* d_out, int out_size) {
    // Size-based binding, correct under any ordering of the three inputs.
    const float* x    = nullptr;
    const float* leaf = nullptr;
    const float* gate = nullptr;
    int batch = 0;
    for (int k = 0; k < n_in; k++) {
        if (in_sizes[k] == 2048)       leaf = (const float*)d_in[k];
        else if (in_sizes[k] == 6138)  gate = (const float*)d_in[k];
        else                           { x = (const float*)d_in[k]; batch = in_sizes[k]; }
    }

    // out_size == batch -> real-part-only float32; >= 2*batch -> interleaved c64.
    const int writeImag = (out_size >= 2 * batch) ? 1 : 0;

    const int nwarps = (batch + NE - 1) / NE;
    const int threads = 128;                  // 4 warps per block
    const int blocks = (nwarps + 3) / 4;

    eml_tree_kernel4<<<blocks, threads>>>(x, leaf, gate, (float*)d_out,
                                          batch, writeImag);
}